// round 2
// baseline (speedup 1.0000x reference)
#include <cuda_runtime.h>
#include <cstdint>

#define N_NODES 100000
#define N_EDGES 600000
#define FEAT    128
#define N_GRAPHS 100
#define BN_EPS  1e-5f
#define SLOTS   64          // padded in-edge capacity per node (Poisson(6) max ~25)

typedef unsigned long long ull;

// ---------------- scratch (device globals: no allocations allowed) ----------
__device__ float g_Y[(size_t)N_NODES * FEAT];     // post-linear activations
__device__ float g_AGG[(size_t)N_NODES * FEAT];   // gathered neighbor sums
__device__ int   g_cnt[N_NODES];                  // per-node in-degree (atomic cursor)
__device__ int   g_slot[(size_t)N_NODES * SLOTS]; // per-node src lists (padded)
__device__ float g_sum[FEAT];
__device__ float g_sumsq[FEAT];
__device__ float g_scale[FEAT];
__device__ float g_shift[FEAT];

// ---------------- helpers ---------------------------------------------------
__device__ __forceinline__ ull pk(float x) {
    ull r; asm("mov.b64 %0, {%1, %1};" : "=l"(r) : "f"(x)); return r;
}
__device__ __forceinline__ void ffma2(ull& d, ull a, ull b) {
    asm("fma.rn.f32x2 %0, %1, %2, %3;" : "=l"(d) : "l"(a), "l"(b), "l"(d));
}
__device__ __forceinline__ float2 up(ull v) {
    float2 p; asm("mov.b64 {%0, %1}, %2;" : "=f"(p.x), "=f"(p.y) : "l"(v)); return p;
}

// ---------------- K0: zero phis, BN accumulators, in-degree counters --------
#define NZERO (N_GRAPHS * FEAT + 2 * FEAT + N_NODES)
__global__ void k_zero(float* __restrict__ phis) {
    int i = blockIdx.x * blockDim.x + threadIdx.x;
    if (i < N_GRAPHS * FEAT)                  phis[i] = 0.f;
    else if (i < N_GRAPHS * FEAT + FEAT)      g_sum[i - N_GRAPHS * FEAT] = 0.f;
    else if (i < N_GRAPHS * FEAT + 2 * FEAT)  g_sumsq[i - N_GRAPHS * FEAT - FEAT] = 0.f;
    else if (i < NZERO)                       g_cnt[i - N_GRAPHS * FEAT - 2 * FEAT] = 0;
}

// ---------------- K1: build per-node src lists ------------------------------
__global__ void k_build(const int* __restrict__ src, const int* __restrict__ dst) {
    int e = blockIdx.x * blockDim.x + threadIdx.x;
    if (e >= N_EDGES) return;
    int d = __ldg(&dst[e]);
    int s = __ldg(&src[e]);
    int pos = atomicAdd(&g_cnt[d], 1);
    g_slot[(size_t)d * SLOTS + pos] = s;
}

// ---------------- K2: gather — agg[v] = sum_{s in nbrs(v)} h[s]*norm[s] -----
__global__ void k_gather(const float* __restrict__ h, const float* __restrict__ norm) {
    int v = blockIdx.x * (blockDim.x >> 5) + (threadIdx.x >> 5);
    if (v >= N_NODES) return;
    int lane = threadIdx.x & 31;
    int c = g_cnt[v];
    const int* slots = g_slot + (size_t)v * SLOTS;

    // prefetch up to 32 (src, norm) pairs lane-distributed, broadcast via shfl
    int   myslot = (lane < c) ? __ldg(&slots[lane]) : 0;
    float mynorm = (lane < c) ? __ldg(&norm[myslot]) : 0.f;

    float4 acc = make_float4(0.f, 0.f, 0.f, 0.f);
    int cc = min(c, 32);
    #pragma unroll 4
    for (int i = 0; i < cc; i++) {
        int   s = __shfl_sync(0xffffffffu, myslot, i);
        float n = __shfl_sync(0xffffffffu, mynorm, i);
        float4 x = __ldg(&((const float4*)(h + (size_t)s * FEAT))[lane]);
        acc.x += x.x * n; acc.y += x.y * n; acc.z += x.z * n; acc.w += x.w * n;
    }
    for (int i = 32; i < c; i++) {          // rare tail (deg > 32)
        int   s = __ldg(&slots[i]);
        float n = __ldg(&norm[s]);
        float4 x = __ldg(&((const float4*)(h + (size_t)s * FEAT))[lane]);
        acc.x += x.x * n; acc.y += x.y * n; acc.z += x.z * n; acc.w += x.w * n;
    }
    ((float4*)(g_AGG + (size_t)v * FEAT))[lane] = acc;
}

// ---------------- K3: Y = relu((agg*norm) @ W + b), fused BN partial stats --
// 512 threads (tx 0..15 cols, ty 0..31 rows), tile 128x128, K=128 full.
// Per thread: 4 rows (2 f32x2 row-pairs) x 8 cols = 16 packed accumulators.
#define AST 132
__global__ void __launch_bounds__(512, 1)
k_gemm(const float* __restrict__ Wg, const float* __restrict__ bg,
       const float* __restrict__ norm) {
    extern __shared__ float sm[];
    float* As = sm;                 // [k][m] k-major, stride AST
    float* Ws = sm + 128 * AST;     // [k][c], stride AST
    int tid = threadIdx.x;
    int rowbase = blockIdx.x * 128;

    // fill A (transpose to k-major, multiply by norm); 4 threads per row
    {
        int r = tid >> 2, q = tid & 3;
        int gr = rowbase + r;
        bool ok = (gr < N_NODES);
        float nm = ok ? __ldg(&norm[gr]) : 0.f;
        const float4* arow = (const float4*)(g_AGG + (size_t)gr * FEAT);
        #pragma unroll
        for (int j = 0; j < 8; j++) {
            int k = q * 32 + j * 4;
            float4 v = ok ? __ldg(&arow[k >> 2]) : make_float4(0.f, 0.f, 0.f, 0.f);
            As[(k + 0) * AST + r] = v.x * nm;
            As[(k + 1) * AST + r] = v.y * nm;
            As[(k + 2) * AST + r] = v.z * nm;
            As[(k + 3) * AST + r] = v.w * nm;
        }
    }
    // fill W (coalesced)
    #pragma unroll
    for (int it = 0; it < 8; it++) {
        int g = tid + 512 * it;            // float4 index, 4096 total
        int k = g >> 5, c = (g & 31) * 4;
        *(float4*)&Ws[k * AST + c] = __ldg(&((const float4*)Wg)[g]);
    }
    __syncthreads();

    int tx = tid & 15, ty = tid >> 4;      // ty 0..31
    int m0 = ty * 4, c0 = tx * 8;

    ull acc[16];
    #pragma unroll
    for (int i = 0; i < 16; i++) acc[i] = 0ull;

    #pragma unroll 8
    for (int k = 0; k < 128; k++) {
        ulonglong2 a01 = *(const ulonglong2*)&As[k * AST + m0];
        const float* wp = &Ws[k * AST + c0];
        float4 w0 = *(const float4*)wp;
        float4 w1 = *(const float4*)(wp + 4);
        ull a2[2] = {a01.x, a01.y};
        ull wd[8] = {pk(w0.x), pk(w0.y), pk(w0.z), pk(w0.w),
                     pk(w1.x), pk(w1.y), pk(w1.z), pk(w1.w)};
        #pragma unroll
        for (int r2 = 0; r2 < 2; r2++)
            #pragma unroll
            for (int c = 0; c < 8; c++)
                ffma2(acc[r2 * 8 + c], a2[r2], wd[c]);
    }

    // epilogue: +bias, relu, store Y, local column stats
    float bv[8];
    #pragma unroll
    for (int c = 0; c < 8; c++) bv[c] = __ldg(&bg[c0 + c]);
    float cs[8], cq[8];
    #pragma unroll
    for (int c = 0; c < 8; c++) { cs[c] = 0.f; cq[c] = 0.f; }

    #pragma unroll
    for (int r2 = 0; r2 < 2; r2++) {
        float2 pr[8];
        #pragma unroll
        for (int c = 0; c < 8; c++) pr[c] = up(acc[r2 * 8 + c]);
        #pragma unroll
        for (int half = 0; half < 2; half++) {
            int row = rowbase + m0 + 2 * r2 + half;
            float o[8];
            #pragma unroll
            for (int c = 0; c < 8; c++) {
                float v = (half ? pr[c].y : pr[c].x) + bv[c];
                o[c] = fmaxf(v, 0.f);
            }
            if (row < N_NODES) {
                *(float4*)&g_Y[(size_t)row * FEAT + c0]     = make_float4(o[0], o[1], o[2], o[3]);
                *(float4*)&g_Y[(size_t)row * FEAT + c0 + 4] = make_float4(o[4], o[5], o[6], o[7]);
                #pragma unroll
                for (int c = 0; c < 8; c++) { cs[c] += o[c]; cq[c] += o[c] * o[c]; }
            }
        }
    }

    // block-level column reduction for BN stats (reuse smem)
    __syncthreads();
    float* S1 = sm;               // [32][128]
    float* S2 = sm + 32 * 128;
    #pragma unroll
    for (int c = 0; c < 8; c++) {
        S1[ty * 128 + c0 + c] = cs[c];
        S2[ty * 128 + c0 + c] = cq[c];
    }
    __syncthreads();
    if (tid < 128) {
        float s = 0.f, q = 0.f;
        #pragma unroll
        for (int y = 0; y < 32; y++) { s += S1[y * 128 + tid]; q += S2[y * 128 + tid]; }
        atomicAdd(&g_sum[tid], s);
        atomicAdd(&g_sumsq[tid], q);
    }
}

// ---------------- K4: finalize BN affine ------------------------------------
__global__ void k_bnfin(const float* __restrict__ gamma, const float* __restrict__ beta) {
    int c = threadIdx.x;
    float mean = g_sum[c] * (1.f / N_NODES);
    float var  = g_sumsq[c] * (1.f / N_NODES) - mean * mean;
    float sc   = gamma[c] * rsqrtf(var + BN_EPS);
    g_scale[c] = sc;
    g_shift[c] = beta[c] - mean * sc;
}

// ---------------- K5: apply BN, write x_out, sorted segment-sum pooling -----
#define OUT_ROWS 256
__global__ void k_out(const int* __restrict__ gid,
                      float* __restrict__ xout, float* __restrict__ phis) {
    int c  = threadIdx.x;                 // 128 threads = one column each
    int r0 = blockIdx.x * OUT_ROWS;
    if (r0 >= N_NODES) return;
    int rend = min(r0 + OUT_ROWS, N_NODES);
    float sc = g_scale[c], sh = g_shift[c];
    float acc = 0.f;
    int gcur = __ldg(&gid[r0]);
    for (int r = r0; r < rend; r++) {
        int g = __ldg(&gid[r]);
        float v = g_Y[(size_t)r * FEAT + c] * sc + sh;
        xout[(size_t)r * FEAT + c] = v;
        if (g != gcur) {
            atomicAdd(&phis[gcur * FEAT + c], acc);
            acc = 0.f; gcur = g;
        }
        acc += v;
    }
    atomicAdd(&phis[gcur * FEAT + c], acc);
}

// ---------------- launch -----------------------------------------------------
extern "C" void kernel_launch(void* const* d_in, const int* in_sizes, int n_in,
                              void* d_out, int out_size) {
    const float* h     = (const float*)d_in[0];
    const float* norm  = (const float*)d_in[1];
    const float* W     = (const float*)d_in[2];
    const float* b     = (const float*)d_in[3];
    const float* gamma = (const float*)d_in[4];
    const float* beta  = (const float*)d_in[5];
    const int*   src   = (const int*)d_in[6];
    const int*   dst   = (const int*)d_in[7];
    const int*   gid   = (const int*)d_in[8];
    float* xout = (float*)d_out;
    float* phis = xout + (size_t)N_NODES * FEAT;

    const int smem_gemm = 2 * 128 * AST * sizeof(float);   // 135168 B
    cudaFuncSetAttribute(k_gemm, cudaFuncAttributeMaxDynamicSharedMemorySize, smem_gemm);

    k_zero<<<(NZERO + 255) / 256, 256>>>(phis);
    k_build<<<(N_EDGES + 255) / 256, 256>>>(src, dst);
    k_gather<<<(N_NODES * 32 + 255) / 256, 256>>>(h, norm);
    k_gemm<<<(N_NODES + 127) / 128, 512, smem_gemm>>>(W, b, norm);
    k_bnfin<<<1, 128>>>(gamma, beta);
    k_out<<<(N_NODES + OUT_ROWS - 1) / OUT_ROWS, 128>>>(gid, xout, phis);
}

// round 3
// speedup vs baseline: 1.4297x; 1.4297x over previous
#include <cuda_runtime.h>
#include <cstdint>

#define N_NODES 100000
#define N_EDGES 600000
#define FEAT    128
#define N_GRAPHS 100
#define BN_EPS  1e-5f
#define SLOTS   64

typedef unsigned long long ull;

// ---------------- scratch (device globals: no allocations allowed) ----------
__device__ float g_Z[(size_t)N_NODES * FEAT];     // Z = (h*norm) @ W
__device__ float g_Y[(size_t)N_NODES * FEAT];     // post-relu activations
__device__ int   g_cnt[N_NODES];                  // per-node in-degree
__device__ int   g_slot[(size_t)N_NODES * SLOTS]; // per-node src lists (padded)
__device__ float g_sum[FEAT];
__device__ float g_sumsq[FEAT];
__device__ float g_scale[FEAT];
__device__ float g_shift[FEAT];

// ---------------- helpers ---------------------------------------------------
__device__ __forceinline__ ull pk(float x) {
    ull r; asm("mov.b64 %0, {%1, %1};" : "=l"(r) : "f"(x)); return r;
}
__device__ __forceinline__ void ffma2(ull& d, ull a, ull b) {
    asm("fma.rn.f32x2 %0, %1, %2, %3;" : "=l"(d) : "l"(a), "l"(b), "l"(d));
}
__device__ __forceinline__ float2 up(ull v) {
    float2 p; asm("mov.b64 {%0, %1}, %2;" : "=f"(p.x), "=f"(p.y) : "l"(v)); return p;
}

// ---------------- K0: zero phis, BN accumulators, in-degree counters --------
#define NZERO (N_GRAPHS * FEAT + 2 * FEAT + N_NODES)
__global__ void k_zero(float* __restrict__ phis) {
    int i = blockIdx.x * blockDim.x + threadIdx.x;
    if (i < N_GRAPHS * FEAT)                  phis[i] = 0.f;
    else if (i < N_GRAPHS * FEAT + FEAT)      g_sum[i - N_GRAPHS * FEAT] = 0.f;
    else if (i < N_GRAPHS * FEAT + 2 * FEAT)  g_sumsq[i - N_GRAPHS * FEAT - FEAT] = 0.f;
    else if (i < NZERO)                       g_cnt[i - N_GRAPHS * FEAT - 2 * FEAT] = 0;
}

// ---------------- K1: build per-node src lists ------------------------------
__global__ void k_build(const int* __restrict__ src, const int* __restrict__ dst) {
    int e = blockIdx.x * blockDim.x + threadIdx.x;
    if (e >= N_EDGES) return;
    int d = __ldg(&dst[e]);
    int s = __ldg(&src[e]);
    int pos = atomicAdd(&g_cnt[d], 1);
    g_slot[(size_t)d * SLOTS + pos] = s;
}

// ---------------- K2: Z = (h*norm) @ W --------------------------------------
// 256 threads = 8 warps. Tile 128x128, K=128 (full).
// Warp w: cols 16w..16w+15 (W reads broadcast). Lane l: rows 4l..4l+3.
// Per thread: 4 rows x 8 col-pairs = 32 f32x2 accumulators.
__global__ void __launch_bounds__(256, 1)
k_gemm(const float* __restrict__ h, const float* __restrict__ norm,
       const float* __restrict__ Wg) {
    extern __shared__ float sm[];
    float* As = sm;             // [k][m], stride 128
    float* Ws = sm + 16384;     // [k][c], stride 128
    int tid = threadIdx.x;
    int rowbase = blockIdx.x * 128;

    // fill A (transpose to k-major, scale by norm); r = tid&127, half = tid>>7
    {
        int r = tid & 127, half = tid >> 7;
        int gr = rowbase + r;
        bool ok = (gr < N_NODES);
        float nm = ok ? __ldg(&norm[gr]) : 0.f;
        const float4* arow = (const float4*)(h + (size_t)gr * FEAT);
        #pragma unroll
        for (int j = 0; j < 16; j++) {
            int k = half * 64 + j * 4;
            float4 v = ok ? __ldg(&arow[k >> 2]) : make_float4(0.f, 0.f, 0.f, 0.f);
            As[(k + 0) * 128 + r] = v.x * nm;
            As[(k + 1) * 128 + r] = v.y * nm;
            As[(k + 2) * 128 + r] = v.z * nm;
            As[(k + 3) * 128 + r] = v.w * nm;
        }
    }
    // fill W (coalesced, [k][c])
    #pragma unroll
    for (int it = 0; it < 16; it++) {
        int g = tid + 256 * it;            // float4 index, 4096 total
        int k = g >> 5, c = (g & 31) * 4;
        *(float4*)&Ws[k * 128 + c] = __ldg(&((const float4*)Wg)[g]);
    }
    __syncthreads();

    int w = tid >> 5, lane = tid & 31;
    int c0 = w * 16, r0 = lane * 4;

    ull acc[32];                 // acc[r*8 + c2]: rows r0+r, cols (c0+2c2, c0+2c2+1)
    #pragma unroll
    for (int i = 0; i < 32; i++) acc[i] = 0ull;

    #pragma unroll 4
    for (int k = 0; k < 128; k++) {
        // A: 4 rows, one LDS.128, duplicate-pack
        float4 av = *(const float4*)&As[k * 128 + r0];
        ull ad[4] = {pk(av.x), pk(av.y), pk(av.z), pk(av.w)};
        // W: 8 col-pairs, broadcast LDS, used raw as f32x2 operands
        const ull* wp = (const ull*)&Ws[k * 128 + c0];
        ull wd[8];
        #pragma unroll
        for (int c2 = 0; c2 < 8; c2++) wd[c2] = wp[c2];
        #pragma unroll
        for (int r = 0; r < 4; r++)
            #pragma unroll
            for (int c2 = 0; c2 < 8; c2++)
                ffma2(acc[r * 8 + c2], ad[r], wd[c2]);
    }

    // store Z rows
    #pragma unroll
    for (int r = 0; r < 4; r++) {
        int row = rowbase + r0 + r;
        if (row < N_NODES) {
            float o[16];
            #pragma unroll
            for (int c2 = 0; c2 < 8; c2++) {
                float2 p = up(acc[r * 8 + c2]);
                o[2 * c2] = p.x; o[2 * c2 + 1] = p.y;
            }
            float* zr = g_Z + (size_t)row * FEAT + c0;
            *(float4*)(zr + 0)  = make_float4(o[0],  o[1],  o[2],  o[3]);
            *(float4*)(zr + 4)  = make_float4(o[4],  o[5],  o[6],  o[7]);
            *(float4*)(zr + 8)  = make_float4(o[8],  o[9],  o[10], o[11]);
            *(float4*)(zr + 12) = make_float4(o[12], o[13], o[14], o[15]);
        }
    }
}

// ---------------- K3: Y[v] = relu(norm[v]*sum_nbr Z[s] + b), BN stats -------
#define GBLK 2048
__global__ void __launch_bounds__(256)
k_gather(const float* __restrict__ norm, const float* __restrict__ bg) {
    __shared__ float S1[8 * 128];
    __shared__ float S2[8 * 128];
    int lane = threadIdx.x & 31;
    int wid  = threadIdx.x >> 5;
    int gw   = blockIdx.x * 8 + wid;
    const int nw = GBLK * 8;

    float4 bv = __ldg(&((const float4*)bg)[lane]);
    float4 cs = make_float4(0.f, 0.f, 0.f, 0.f);
    float4 cq = make_float4(0.f, 0.f, 0.f, 0.f);

    for (int v = gw; v < N_NODES; v += nw) {
        int c = g_cnt[v];
        const int* slots = g_slot + (size_t)v * SLOTS;
        int myslot = (lane < c) ? __ldg(&slots[lane]) : 0;

        float4 acc = make_float4(0.f, 0.f, 0.f, 0.f);
        int cc = min(c, 32);
        #pragma unroll 4
        for (int i = 0; i < cc; i++) {
            int s = __shfl_sync(0xffffffffu, myslot, i);
            float4 z = __ldg(&((const float4*)(g_Z + (size_t)s * FEAT))[lane]);
            acc.x += z.x; acc.y += z.y; acc.z += z.z; acc.w += z.w;
        }
        for (int i = 32; i < c; i++) {      // rare tail
            int s = __ldg(&slots[i]);
            float4 z = __ldg(&((const float4*)(g_Z + (size_t)s * FEAT))[lane]);
            acc.x += z.x; acc.y += z.y; acc.z += z.z; acc.w += z.w;
        }
        float nm = __ldg(&norm[v]);
        float4 y;
        y.x = fmaxf(acc.x * nm + bv.x, 0.f);
        y.y = fmaxf(acc.y * nm + bv.y, 0.f);
        y.z = fmaxf(acc.z * nm + bv.z, 0.f);
        y.w = fmaxf(acc.w * nm + bv.w, 0.f);
        ((float4*)(g_Y + (size_t)v * FEAT))[lane] = y;
        cs.x += y.x; cs.y += y.y; cs.z += y.z; cs.w += y.w;
        cq.x += y.x * y.x; cq.y += y.y * y.y; cq.z += y.z * y.z; cq.w += y.w * y.w;
    }

    // block-level BN stat reduction
    *(float4*)&S1[wid * 128 + lane * 4] = cs;
    *(float4*)&S2[wid * 128 + lane * 4] = cq;
    __syncthreads();
    int tid = threadIdx.x;
    if (tid < 128) {
        float s = 0.f, q = 0.f;
        #pragma unroll
        for (int y = 0; y < 8; y++) { s += S1[y * 128 + tid]; q += S2[y * 128 + tid]; }
        atomicAdd(&g_sum[tid], s);
        atomicAdd(&g_sumsq[tid], q);
    }
}

// ---------------- K4: finalize BN affine ------------------------------------
__global__ void k_bnfin(const float* __restrict__ gamma, const float* __restrict__ beta) {
    int c = threadIdx.x;
    float mean = g_sum[c] * (1.f / N_NODES);
    float var  = g_sumsq[c] * (1.f / N_NODES) - mean * mean;
    float sc   = gamma[c] * rsqrtf(var + BN_EPS);
    g_scale[c] = sc;
    g_shift[c] = beta[c] - mean * sc;
}

// ---------------- K5: apply BN, write x_out, sorted segment-sum pooling -----
#define OUT_ROWS 128
__global__ void k_out(const int* __restrict__ gid,
                      float* __restrict__ xout, float* __restrict__ phis) {
    int c  = threadIdx.x;                 // 128 threads = one column each
    int r0 = blockIdx.x * OUT_ROWS;
    if (r0 >= N_NODES) return;
    int rend = min(r0 + OUT_ROWS, N_NODES);
    float sc = g_scale[c], sh = g_shift[c];
    float acc = 0.f;
    int gcur = __ldg(&gid[r0]);
    #pragma unroll 4
    for (int r = r0; r < rend; r++) {
        int g = __ldg(&gid[r]);
        float v = g_Y[(size_t)r * FEAT + c] * sc + sh;
        xout[(size_t)r * FEAT + c] = v;
        if (g != gcur) {
            atomicAdd(&phis[gcur * FEAT + c], acc);
            acc = 0.f; gcur = g;
        }
        acc += v;
    }
    atomicAdd(&phis[gcur * FEAT + c], acc);
}

// ---------------- launch -----------------------------------------------------
extern "C" void kernel_launch(void* const* d_in, const int* in_sizes, int n_in,
                              void* d_out, int out_size) {
    const float* h     = (const float*)d_in[0];
    const float* norm  = (const float*)d_in[1];
    const float* W     = (const float*)d_in[2];
    const float* b     = (const float*)d_in[3];
    const float* gamma = (const float*)d_in[4];
    const float* beta  = (const float*)d_in[5];
    const int*   src   = (const int*)d_in[6];
    const int*   dst   = (const int*)d_in[7];
    const int*   gid   = (const int*)d_in[8];
    float* xout = (float*)d_out;
    float* phis = xout + (size_t)N_NODES * FEAT;

    const int smem_gemm = 2 * 128 * 128 * sizeof(float);   // 131072 B
    cudaFuncSetAttribute(k_gemm, cudaFuncAttributeMaxDynamicSharedMemorySize, smem_gemm);

    k_zero<<<(NZERO + 255) / 256, 256>>>(phis);
    k_build<<<(N_EDGES + 255) / 256, 256>>>(src, dst);
    k_gemm<<<(N_NODES + 127) / 128, 256, smem_gemm>>>(h, norm, W);
    k_gather<<<GBLK, 256>>>(norm, b);
    k_bnfin<<<1, 128>>>(gamma, beta);
    k_out<<<(N_NODES + OUT_ROWS - 1) / OUT_ROWS, 128>>>(gid, xout, phis);
}

// round 4
// speedup vs baseline: 1.6628x; 1.1630x over previous
#include <cuda_runtime.h>
#include <cuda_fp16.h>
#include <cstdint>

#define N_NODES 100000
#define N_EDGES 600000
#define FEAT    128
#define N_GRAPHS 100
#define BN_EPS  1e-5f
#define SLOTS   64

typedef unsigned long long ull;
typedef unsigned int uint;

// ---------------- scratch (device globals: no allocations allowed) ----------
__device__ uint  g_Z[(size_t)N_NODES * 64];       // Z = (h*norm)@W, half2-packed
__device__ float g_Y[(size_t)N_NODES * FEAT];     // post-relu activations (fp32)
__device__ int   g_cnt[N_NODES];                  // per-node in-degree
__device__ int   g_slot[(size_t)N_NODES * SLOTS]; // per-node src lists (padded)
__device__ float g_sum[FEAT];
__device__ float g_sumsq[FEAT];
__device__ float g_scale[FEAT];
__device__ float g_shift[FEAT];

// ---------------- helpers ---------------------------------------------------
__device__ __forceinline__ ull pk(float x) {
    ull r; asm("mov.b64 %0, {%1, %1};" : "=l"(r) : "f"(x)); return r;
}
__device__ __forceinline__ void ffma2(ull& d, ull a, ull b) {
    asm("fma.rn.f32x2 %0, %1, %2, %3;" : "=l"(d) : "l"(a), "l"(b), "l"(d));
}
__device__ __forceinline__ float2 up(ull v) {
    float2 p; asm("mov.b64 {%0, %1}, %2;" : "=f"(p.x), "=f"(p.y) : "l"(v)); return p;
}

// ---------------- K0: zero phis, BN accumulators, in-degree counters --------
#define NZERO (N_GRAPHS * FEAT + 2 * FEAT + N_NODES)
__global__ void k_zero(float* __restrict__ phis) {
    int i = blockIdx.x * blockDim.x + threadIdx.x;
    if (i < N_GRAPHS * FEAT)                  phis[i] = 0.f;
    else if (i < N_GRAPHS * FEAT + FEAT)      g_sum[i - N_GRAPHS * FEAT] = 0.f;
    else if (i < N_GRAPHS * FEAT + 2 * FEAT)  g_sumsq[i - N_GRAPHS * FEAT - FEAT] = 0.f;
    else if (i < NZERO)                       g_cnt[i - N_GRAPHS * FEAT - 2 * FEAT] = 0;
}

// ---------------- K1: build per-node src lists ------------------------------
__global__ void k_build(const int* __restrict__ src, const int* __restrict__ dst) {
    int e = blockIdx.x * blockDim.x + threadIdx.x;
    if (e >= N_EDGES) return;
    int d = __ldg(&dst[e]);
    int s = __ldg(&src[e]);
    int pos = atomicAdd(&g_cnt[d], 1);
    g_slot[(size_t)d * SLOTS + pos] = s;
}

// ---------------- K2: Z = (h*norm) @ W  (fp16 output) -----------------------
// 256 threads = 8 warps. Tile 128x128, K=128 full.
// Warp w: cols 16w..16w+15 (broadcast W). Lane l: rows 4l..4l+3.
__global__ void __launch_bounds__(256, 1)
k_gemm(const float* __restrict__ h, const float* __restrict__ norm,
       const float* __restrict__ Wg) {
    extern __shared__ float sm[];
    float* As = sm;             // [k][m], stride 128
    float* Ws = sm + 16384;     // [k][c], stride 128
    int tid = threadIdx.x;
    int rowbase = blockIdx.x * 128;

    {
        int r = tid & 127, half = tid >> 7;
        int gr = rowbase + r;
        bool ok = (gr < N_NODES);
        float nm = ok ? __ldg(&norm[gr]) : 0.f;
        const float4* arow = (const float4*)(h + (size_t)gr * FEAT);
        #pragma unroll
        for (int j = 0; j < 16; j++) {
            int k = half * 64 + j * 4;
            float4 v = ok ? __ldg(&arow[k >> 2]) : make_float4(0.f, 0.f, 0.f, 0.f);
            As[(k + 0) * 128 + r] = v.x * nm;
            As[(k + 1) * 128 + r] = v.y * nm;
            As[(k + 2) * 128 + r] = v.z * nm;
            As[(k + 3) * 128 + r] = v.w * nm;
        }
    }
    #pragma unroll
    for (int it = 0; it < 16; it++) {
        int g = tid + 256 * it;            // float4 index, 4096 total
        int k = g >> 5, c = (g & 31) * 4;
        *(float4*)&Ws[k * 128 + c] = __ldg(&((const float4*)Wg)[g]);
    }
    __syncthreads();

    int w = tid >> 5, lane = tid & 31;
    int c0 = w * 16, r0 = lane * 4;

    ull acc[32];
    #pragma unroll
    for (int i = 0; i < 32; i++) acc[i] = 0ull;

    #pragma unroll 4
    for (int k = 0; k < 128; k++) {
        float4 av = *(const float4*)&As[k * 128 + r0];
        ull ad[4] = {pk(av.x), pk(av.y), pk(av.z), pk(av.w)};
        const ull* wp = (const ull*)&Ws[k * 128 + c0];
        ull wd[8];
        #pragma unroll
        for (int c2 = 0; c2 < 8; c2++) wd[c2] = wp[c2];
        #pragma unroll
        for (int r = 0; r < 4; r++)
            #pragma unroll
            for (int c2 = 0; c2 < 8; c2++)
                ffma2(acc[r * 8 + c2], ad[r], wd[c2]);
    }

    // store Z rows as half2
    #pragma unroll
    for (int r = 0; r < 4; r++) {
        int row = rowbase + r0 + r;
        if (row < N_NODES) {
            uint st[8];
            #pragma unroll
            for (int c2 = 0; c2 < 8; c2++) {
                float2 p = up(acc[r * 8 + c2]);
                __half2 hv = __floats2half2_rn(p.x, p.y);   // low = even col
                st[c2] = *(uint*)&hv;
            }
            uint* zr = g_Z + (size_t)row * 64 + c0 / 2;
            ((uint4*)zr)[0] = make_uint4(st[0], st[1], st[2], st[3]);
            ((uint4*)zr)[1] = make_uint4(st[4], st[5], st[6], st[7]);
        }
    }
}

// ---------------- K3: Y[v] = relu(norm[v]*sum_nbr Z[s] + b), BN stats -------
// One warp handles a PAIR of nodes (interleaved loads => 2x MLP).
#define GBLK 2048
__device__ __forceinline__ void acc_z(float4& a, int s, int lane) {
    uint2 q = __ldg(&((const uint2*)(g_Z + (size_t)s * 64))[lane]);
    float2 f0 = __half22float2(*(__half2*)&q.x);
    float2 f1 = __half22float2(*(__half2*)&q.y);
    a.x += f0.x; a.y += f0.y; a.z += f1.x; a.w += f1.y;
}
__global__ void __launch_bounds__(256)
k_gather(const float* __restrict__ norm, const float* __restrict__ bg) {
    __shared__ float S1[8 * 128];
    __shared__ float S2[8 * 128];
    int lane = threadIdx.x & 31;
    int wid  = threadIdx.x >> 5;
    int gw   = blockIdx.x * 8 + wid;
    const int nw = GBLK * 8;

    float4 bv = __ldg(&((const float4*)bg)[lane]);
    float4 cs = make_float4(0.f, 0.f, 0.f, 0.f);
    float4 cq = make_float4(0.f, 0.f, 0.f, 0.f);

    for (int v0 = gw * 2; v0 < N_NODES; v0 += nw * 2) {
        int v1 = v0 + 1;                       // N_NODES even -> always valid
        int c0 = g_cnt[v0], c1 = g_cnt[v1];
        const int* sl0 = g_slot + (size_t)v0 * SLOTS;
        const int* sl1 = g_slot + (size_t)v1 * SLOTS;
        int ms0 = (lane < c0) ? __ldg(&sl0[lane]) : 0;
        int ms1 = (lane < c1) ? __ldg(&sl1[lane]) : 0;

        float4 a0 = make_float4(0.f, 0.f, 0.f, 0.f);
        float4 a1 = make_float4(0.f, 0.f, 0.f, 0.f);
        int cc0 = min(c0, 32), cc1 = min(c1, 32);
        int m = max(cc0, cc1);
        #pragma unroll 4
        for (int i = 0; i < m; i++) {
            if (i < cc0) { int s = __shfl_sync(0xffffffffu, ms0, i); acc_z(a0, s, lane); }
            if (i < cc1) { int s = __shfl_sync(0xffffffffu, ms1, i); acc_z(a1, s, lane); }
        }
        for (int i = 32; i < c0; i++) { int s = __ldg(&sl0[i]); acc_z(a0, s, lane); }
        for (int i = 32; i < c1; i++) { int s = __ldg(&sl1[i]); acc_z(a1, s, lane); }

        float n0 = __ldg(&norm[v0]);
        float n1 = __ldg(&norm[v1]);
        float4 y0, y1;
        y0.x = fmaxf(a0.x * n0 + bv.x, 0.f); y0.y = fmaxf(a0.y * n0 + bv.y, 0.f);
        y0.z = fmaxf(a0.z * n0 + bv.z, 0.f); y0.w = fmaxf(a0.w * n0 + bv.w, 0.f);
        y1.x = fmaxf(a1.x * n1 + bv.x, 0.f); y1.y = fmaxf(a1.y * n1 + bv.y, 0.f);
        y1.z = fmaxf(a1.z * n1 + bv.z, 0.f); y1.w = fmaxf(a1.w * n1 + bv.w, 0.f);
        ((float4*)(g_Y + (size_t)v0 * FEAT))[lane] = y0;
        ((float4*)(g_Y + (size_t)v1 * FEAT))[lane] = y1;
        cs.x += y0.x + y1.x; cs.y += y0.y + y1.y;
        cs.z += y0.z + y1.z; cs.w += y0.w + y1.w;
        cq.x += y0.x * y0.x + y1.x * y1.x; cq.y += y0.y * y0.y + y1.y * y1.y;
        cq.z += y0.z * y0.z + y1.z * y1.z; cq.w += y0.w * y0.w + y1.w * y1.w;
    }

    *(float4*)&S1[wid * 128 + lane * 4] = cs;
    *(float4*)&S2[wid * 128 + lane * 4] = cq;
    __syncthreads();
    int tid = threadIdx.x;
    if (tid < 128) {
        float s = 0.f, q = 0.f;
        #pragma unroll
        for (int y = 0; y < 8; y++) { s += S1[y * 128 + tid]; q += S2[y * 128 + tid]; }
        atomicAdd(&g_sum[tid], s);
        atomicAdd(&g_sumsq[tid], q);
    }
}

// ---------------- K4: finalize BN affine ------------------------------------
__global__ void k_bnfin(const float* __restrict__ gamma, const float* __restrict__ beta) {
    int c = threadIdx.x;
    float mean = g_sum[c] * (1.f / N_NODES);
    float var  = g_sumsq[c] * (1.f / N_NODES) - mean * mean;
    float sc   = gamma[c] * rsqrtf(var + BN_EPS);
    g_scale[c] = sc;
    g_shift[c] = beta[c] - mean * sc;
}

// ---------------- K5: apply BN, write x_out, sorted segment-sum pooling -----
// Warp per 64-row chunk; lane owns a float4 column group (vectorized).
#define OCHUNK 64
__global__ void __launch_bounds__(256)
k_out(const int* __restrict__ gid, float* __restrict__ xout, float* __restrict__ phis) {
    int lane = threadIdx.x & 31;
    int wid  = threadIdx.x >> 5;
    int chunk = blockIdx.x * 8 + wid;
    int r0 = chunk * OCHUNK;
    if (r0 >= N_NODES) return;
    int rend = min(r0 + OCHUNK, N_NODES);

    float4 sc = *(const float4*)&g_scale[lane * 4];
    float4 sh = *(const float4*)&g_shift[lane * 4];
    float4 acc = make_float4(0.f, 0.f, 0.f, 0.f);
    int gcur = __ldg(&gid[r0]);

    #pragma unroll 4
    for (int r = r0; r < rend; r++) {
        int g = __ldg(&gid[r]);
        float4 y = ((const float4*)(g_Y + (size_t)r * FEAT))[lane];
        float4 v;
        v.x = y.x * sc.x + sh.x; v.y = y.y * sc.y + sh.y;
        v.z = y.z * sc.z + sh.z; v.w = y.w * sc.w + sh.w;
        ((float4*)(xout + (size_t)r * FEAT))[lane] = v;
        if (g != gcur) {
            float* pp = phis + (size_t)gcur * FEAT + lane * 4;
            atomicAdd(pp + 0, acc.x); atomicAdd(pp + 1, acc.y);
            atomicAdd(pp + 2, acc.z); atomicAdd(pp + 3, acc.w);
            acc = make_float4(0.f, 0.f, 0.f, 0.f);
            gcur = g;
        }
        acc.x += v.x; acc.y += v.y; acc.z += v.z; acc.w += v.w;
    }
    float* pp = phis + (size_t)gcur * FEAT + lane * 4;
    atomicAdd(pp + 0, acc.x); atomicAdd(pp + 1, acc.y);
    atomicAdd(pp + 2, acc.z); atomicAdd(pp + 3, acc.w);
}

// ---------------- launch -----------------------------------------------------
extern "C" void kernel_launch(void* const* d_in, const int* in_sizes, int n_in,
                              void* d_out, int out_size) {
    const float* h     = (const float*)d_in[0];
    const float* norm  = (const float*)d_in[1];
    const float* W     = (const float*)d_in[2];
    const float* b     = (const float*)d_in[3];
    const float* gamma = (const float*)d_in[4];
    const float* beta  = (const float*)d_in[5];
    const int*   src   = (const int*)d_in[6];
    const int*   dst   = (const int*)d_in[7];
    const int*   gid   = (const int*)d_in[8];
    float* xout = (float*)d_out;
    float* phis = xout + (size_t)N_NODES * FEAT;

    const int smem_gemm = 2 * 128 * 128 * sizeof(float);   // 131072 B
    cudaFuncSetAttribute(k_gemm, cudaFuncAttributeMaxDynamicSharedMemorySize, smem_gemm);

    k_zero<<<(NZERO + 255) / 256, 256>>>(phis);
    k_build<<<(N_EDGES + 255) / 256, 256>>>(src, dst);
    k_gemm<<<(N_NODES + 127) / 128, 256, smem_gemm>>>(h, norm, W);
    k_gather<<<GBLK, 256>>>(norm, b);
    k_bnfin<<<1, 128>>>(gamma, beta);
    k_out<<<(N_NODES + OCHUNK * 8 - 1) / (OCHUNK * 8), 256>>>(gid, xout, phis);
}

// round 5
// speedup vs baseline: 1.6768x; 1.0084x over previous
#include <cuda_runtime.h>
#include <cuda_fp16.h>
#include <cstdint>

#define N_NODES 100000
#define N_EDGES 600000
#define FEAT    128
#define N_GRAPHS 100
#define BN_EPS  1e-5f
#define SLOTS   64

typedef unsigned long long ull;
typedef unsigned int uint;

// ---------------- scratch (device globals: no allocations allowed) ----------
__device__ uint  g_Z[(size_t)N_NODES * 64];       // Z = (h*norm)@W, half2-packed
__device__ float g_Y[(size_t)N_NODES * FEAT];     // post-relu activations (fp32)
__device__ int   g_cnt[N_NODES];                  // per-node in-degree
__device__ int   g_slot[(size_t)N_NODES * SLOTS]; // per-node src lists (padded)
__device__ float g_sum[FEAT];
__device__ float g_sumsq[FEAT];
__device__ float g_scale[FEAT];
__device__ float g_shift[FEAT];

// ---------------- helpers ---------------------------------------------------
__device__ __forceinline__ ull pk(float x) {
    ull r; asm("mov.b64 %0, {%1, %1};" : "=l"(r) : "f"(x)); return r;
}
__device__ __forceinline__ void ffma2(ull& d, ull a, ull b) {
    asm("fma.rn.f32x2 %0, %1, %2, %3;" : "=l"(d) : "l"(a), "l"(b), "l"(d));
}
__device__ __forceinline__ float2 up(ull v) {
    float2 p; asm("mov.b64 {%0, %1}, %2;" : "=f"(p.x), "=f"(p.y) : "l"(v)); return p;
}

// ---------------- K0: zero phis, BN accumulators, in-degree counters --------
#define NZERO (N_GRAPHS * FEAT + 2 * FEAT + N_NODES)
__global__ void k_zero(float* __restrict__ phis) {
    int i = blockIdx.x * blockDim.x + threadIdx.x;
    if (i < N_GRAPHS * FEAT)                  phis[i] = 0.f;
    else if (i < N_GRAPHS * FEAT + FEAT)      g_sum[i - N_GRAPHS * FEAT] = 0.f;
    else if (i < N_GRAPHS * FEAT + 2 * FEAT)  g_sumsq[i - N_GRAPHS * FEAT - FEAT] = 0.f;
    else if (i < NZERO)                       g_cnt[i - N_GRAPHS * FEAT - 2 * FEAT] = 0;
}

// ---------------- K1: build per-node src lists ------------------------------
__global__ void k_build(const int* __restrict__ src, const int* __restrict__ dst) {
    int e = blockIdx.x * blockDim.x + threadIdx.x;
    if (e >= N_EDGES) return;
    int d = __ldg(&dst[e]);
    int s = __ldg(&src[e]);
    int pos = atomicAdd(&g_cnt[d], 1);
    g_slot[(size_t)d * SLOTS + pos] = s;
}

// ---------------- K2: Z = (h*norm) @ W  (fp16 output) -----------------------
// 256 threads = 8 warps. Tile 128x128, K=128 full.
// Warp w: cols 16w..16w+15 (broadcast W). Lane l: rows 4l..4l+3.
__global__ void __launch_bounds__(256, 1)
k_gemm(const float* __restrict__ h, const float* __restrict__ norm,
       const float* __restrict__ Wg) {
    extern __shared__ float sm[];
    float* As = sm;             // [k][m], stride 128
    float* Ws = sm + 16384;     // [k][c], stride 128
    int tid = threadIdx.x;
    int rowbase = blockIdx.x * 128;

    {
        int r = tid & 127, half = tid >> 7;
        int gr = rowbase + r;
        bool ok = (gr < N_NODES);
        float nm = ok ? __ldg(&norm[gr]) : 0.f;
        const float4* arow = (const float4*)(h + (size_t)gr * FEAT);
        #pragma unroll
        for (int j = 0; j < 16; j++) {
            int k = half * 64 + j * 4;
            float4 v = ok ? __ldg(&arow[k >> 2]) : make_float4(0.f, 0.f, 0.f, 0.f);
            As[(k + 0) * 128 + r] = v.x * nm;
            As[(k + 1) * 128 + r] = v.y * nm;
            As[(k + 2) * 128 + r] = v.z * nm;
            As[(k + 3) * 128 + r] = v.w * nm;
        }
    }
    #pragma unroll
    for (int it = 0; it < 16; it++) {
        int g = tid + 256 * it;            // float4 index, 4096 total
        int k = g >> 5, c = (g & 31) * 4;
        *(float4*)&Ws[k * 128 + c] = __ldg(&((const float4*)Wg)[g]);
    }
    __syncthreads();

    int w = tid >> 5, lane = tid & 31;
    int c0 = w * 16, r0 = lane * 4;

    ull acc[32];
    #pragma unroll
    for (int i = 0; i < 32; i++) acc[i] = 0ull;

    #pragma unroll 4
    for (int k = 0; k < 128; k++) {
        float4 av = *(const float4*)&As[k * 128 + r0];
        ull ad[4] = {pk(av.x), pk(av.y), pk(av.z), pk(av.w)};
        const ull* wp = (const ull*)&Ws[k * 128 + c0];
        ull wd[8];
        #pragma unroll
        for (int c2 = 0; c2 < 8; c2++) wd[c2] = wp[c2];
        #pragma unroll
        for (int r = 0; r < 4; r++)
            #pragma unroll
            for (int c2 = 0; c2 < 8; c2++)
                ffma2(acc[r * 8 + c2], ad[r], wd[c2]);
    }

    // store Z rows as half2
    #pragma unroll
    for (int r = 0; r < 4; r++) {
        int row = rowbase + r0 + r;
        if (row < N_NODES) {
            uint st[8];
            #pragma unroll
            for (int c2 = 0; c2 < 8; c2++) {
                float2 p = up(acc[r * 8 + c2]);
                __half2 hv = __floats2half2_rn(p.x, p.y);   // low = even col
                st[c2] = *(uint*)&hv;
            }
            uint* zr = g_Z + (size_t)row * 64 + c0 / 2;
            ((uint4*)zr)[0] = make_uint4(st[0], st[1], st[2], st[3]);
            ((uint4*)zr)[1] = make_uint4(st[4], st[5], st[6], st[7]);
        }
    }
}

// ---------------- K3: Y[v] = relu(norm[v]*sum_nbr Z[s] + b), BN stats -------
// One warp handles FOUR nodes (4 independent chains => ~16 loads in flight).
// Exact partition: 3125 blocks x 8 warps x 4 nodes = 100000.
#define GBLK 3125
__device__ __forceinline__ void acc_z(float4& a, int s, int lane) {
    uint2 q = __ldg(&((const uint2*)(g_Z + (size_t)s * 64))[lane]);
    float2 f0 = __half22float2(*(__half2*)&q.x);
    float2 f1 = __half22float2(*(__half2*)&q.y);
    a.x += f0.x; a.y += f0.y; a.z += f1.x; a.w += f1.y;
}
__global__ void __launch_bounds__(256)
k_gather(const float* __restrict__ norm, const float* __restrict__ bg) {
    __shared__ float S1[8 * 128];
    __shared__ float S2[8 * 128];
    int lane = threadIdx.x & 31;
    int wid  = threadIdx.x >> 5;
    int v0 = (blockIdx.x * 8 + wid) * 4;    // 4 consecutive nodes per warp

    float4 bv = __ldg(&((const float4*)bg)[lane]);

    // counts + slot prefetch for all 4 nodes (independent loads, issued early)
    int c0 = __ldg(&g_cnt[v0 + 0]);
    int c1 = __ldg(&g_cnt[v0 + 1]);
    int c2 = __ldg(&g_cnt[v0 + 2]);
    int c3 = __ldg(&g_cnt[v0 + 3]);
    const int* sl0 = g_slot + (size_t)(v0 + 0) * SLOTS;
    const int* sl1 = g_slot + (size_t)(v0 + 1) * SLOTS;
    const int* sl2 = g_slot + (size_t)(v0 + 2) * SLOTS;
    const int* sl3 = g_slot + (size_t)(v0 + 3) * SLOTS;
    int ms0 = (lane < c0) ? __ldg(&sl0[lane]) : 0;
    int ms1 = (lane < c1) ? __ldg(&sl1[lane]) : 0;
    int ms2 = (lane < c2) ? __ldg(&sl2[lane]) : 0;
    int ms3 = (lane < c3) ? __ldg(&sl3[lane]) : 0;

    float4 a0 = make_float4(0.f, 0.f, 0.f, 0.f);
    float4 a1 = make_float4(0.f, 0.f, 0.f, 0.f);
    float4 a2 = make_float4(0.f, 0.f, 0.f, 0.f);
    float4 a3 = make_float4(0.f, 0.f, 0.f, 0.f);
    int cc0 = min(c0, 32), cc1 = min(c1, 32);
    int cc2 = min(c2, 32), cc3 = min(c3, 32);
    int m = max(max(cc0, cc1), max(cc2, cc3));
    #pragma unroll 2
    for (int i = 0; i < m; i++) {
        if (i < cc0) { int s = __shfl_sync(0xffffffffu, ms0, i); acc_z(a0, s, lane); }
        if (i < cc1) { int s = __shfl_sync(0xffffffffu, ms1, i); acc_z(a1, s, lane); }
        if (i < cc2) { int s = __shfl_sync(0xffffffffu, ms2, i); acc_z(a2, s, lane); }
        if (i < cc3) { int s = __shfl_sync(0xffffffffu, ms3, i); acc_z(a3, s, lane); }
    }
    for (int i = 32; i < c0; i++) { int s = __ldg(&sl0[i]); acc_z(a0, s, lane); }
    for (int i = 32; i < c1; i++) { int s = __ldg(&sl1[i]); acc_z(a1, s, lane); }
    for (int i = 32; i < c2; i++) { int s = __ldg(&sl2[i]); acc_z(a2, s, lane); }
    for (int i = 32; i < c3; i++) { int s = __ldg(&sl3[i]); acc_z(a3, s, lane); }

    float n0 = __ldg(&norm[v0 + 0]);
    float n1 = __ldg(&norm[v0 + 1]);
    float n2 = __ldg(&norm[v0 + 2]);
    float n3 = __ldg(&norm[v0 + 3]);

    float4 cs = make_float4(0.f, 0.f, 0.f, 0.f);
    float4 cq = make_float4(0.f, 0.f, 0.f, 0.f);
    float4 acc[4] = {a0, a1, a2, a3};
    float  nn[4]  = {n0, n1, n2, n3};
    #pragma unroll
    for (int j = 0; j < 4; j++) {
        float4 y;
        y.x = fmaxf(acc[j].x * nn[j] + bv.x, 0.f);
        y.y = fmaxf(acc[j].y * nn[j] + bv.y, 0.f);
        y.z = fmaxf(acc[j].z * nn[j] + bv.z, 0.f);
        y.w = fmaxf(acc[j].w * nn[j] + bv.w, 0.f);
        ((float4*)(g_Y + (size_t)(v0 + j) * FEAT))[lane] = y;
        cs.x += y.x; cs.y += y.y; cs.z += y.z; cs.w += y.w;
        cq.x += y.x * y.x; cq.y += y.y * y.y;
        cq.z += y.z * y.z; cq.w += y.w * y.w;
    }

    *(float4*)&S1[wid * 128 + lane * 4] = cs;
    *(float4*)&S2[wid * 128 + lane * 4] = cq;
    __syncthreads();
    int tid = threadIdx.x;
    if (tid < 128) {
        float s = 0.f, q = 0.f;
        #pragma unroll
        for (int y = 0; y < 8; y++) { s += S1[y * 128 + tid]; q += S2[y * 128 + tid]; }
        atomicAdd(&g_sum[tid], s);
        atomicAdd(&g_sumsq[tid], q);
    }
}

// ---------------- K4: finalize BN affine ------------------------------------
__global__ void k_bnfin(const float* __restrict__ gamma, const float* __restrict__ beta) {
    int c = threadIdx.x;
    float mean = g_sum[c] * (1.f / N_NODES);
    float var  = g_sumsq[c] * (1.f / N_NODES) - mean * mean;
    float sc   = gamma[c] * rsqrtf(var + BN_EPS);
    g_scale[c] = sc;
    g_shift[c] = beta[c] - mean * sc;
}

// ---------------- K5: apply BN, write x_out, sorted segment-sum pooling -----
// Warp per 64-row chunk; lane owns a float4 column group (vectorized).
#define OCHUNK 64
__global__ void __launch_bounds__(256)
k_out(const int* __restrict__ gid, float* __restrict__ xout, float* __restrict__ phis) {
    int lane = threadIdx.x & 31;
    int wid  = threadIdx.x >> 5;
    int chunk = blockIdx.x * 8 + wid;
    int r0 = chunk * OCHUNK;
    if (r0 >= N_NODES) return;
    int rend = min(r0 + OCHUNK, N_NODES);

    float4 sc = *(const float4*)&g_scale[lane * 4];
    float4 sh = *(const float4*)&g_shift[lane * 4];
    float4 acc = make_float4(0.f, 0.f, 0.f, 0.f);
    int gcur = __ldg(&gid[r0]);

    #pragma unroll 4
    for (int r = r0; r < rend; r++) {
        int g = __ldg(&gid[r]);
        float4 y = ((const float4*)(g_Y + (size_t)r * FEAT))[lane];
        float4 v;
        v.x = y.x * sc.x + sh.x; v.y = y.y * sc.y + sh.y;
        v.z = y.z * sc.z + sh.z; v.w = y.w * sc.w + sh.w;
        ((float4*)(xout + (size_t)r * FEAT))[lane] = v;
        if (g != gcur) {
            float* pp = phis + (size_t)gcur * FEAT + lane * 4;
            atomicAdd(pp + 0, acc.x); atomicAdd(pp + 1, acc.y);
            atomicAdd(pp + 2, acc.z); atomicAdd(pp + 3, acc.w);
            acc = make_float4(0.f, 0.f, 0.f, 0.f);
            gcur = g;
        }
        acc.x += v.x; acc.y += v.y; acc.z += v.z; acc.w += v.w;
    }
    float* pp = phis + (size_t)gcur * FEAT + lane * 4;
    atomicAdd(pp + 0, acc.x); atomicAdd(pp + 1, acc.y);
    atomicAdd(pp + 2, acc.z); atomicAdd(pp + 3, acc.w);
}

// ---------------- launch -----------------------------------------------------
extern "C" void kernel_launch(void* const* d_in, const int* in_sizes, int n_in,
                              void* d_out, int out_size) {
    const float* h     = (const float*)d_in[0];
    const float* norm  = (const float*)d_in[1];
    const float* W     = (const float*)d_in[2];
    const float* b     = (const float*)d_in[3];
    const float* gamma = (const float*)d_in[4];
    const float* beta  = (const float*)d_in[5];
    const int*   src   = (const int*)d_in[6];
    const int*   dst   = (const int*)d_in[7];
    const int*   gid   = (const int*)d_in[8];
    float* xout = (float*)d_out;
    float* phis = xout + (size_t)N_NODES * FEAT;

    const int smem_gemm = 2 * 128 * 128 * sizeof(float);   // 131072 B
    cudaFuncSetAttribute(k_gemm, cudaFuncAttributeMaxDynamicSharedMemorySize, smem_gemm);

    k_zero<<<(NZERO + 255) / 256, 256>>>(phis);
    k_build<<<(N_EDGES + 255) / 256, 256>>>(src, dst);
    k_gemm<<<(N_NODES + 127) / 128, 256, smem_gemm>>>(h, norm, W);
    k_gather<<<GBLK, 256>>>(norm, b);
    k_bnfin<<<1, 128>>>(gamma, beta);
    k_out<<<(N_NODES + OCHUNK * 8 - 1) / (OCHUNK * 8), 256>>>(gid, xout, phis);
}

// round 7
// speedup vs baseline: 1.6873x; 1.0063x over previous
#include <cuda_runtime.h>
#include <cuda_fp16.h>
#include <cstdint>

#define N_NODES 100000
#define N_EDGES 600000
#define FEAT    128
#define N_GRAPHS 100
#define BN_EPS  1e-5f
#define SLOTS   64

typedef unsigned long long ull;
typedef unsigned int uint;

// ---------------- scratch (device globals: no allocations allowed) ----------
__device__ uint  g_Z[(size_t)N_NODES * 64];       // Z = (h*norm)@W, half2-packed
__device__ float g_Y[(size_t)N_NODES * FEAT];     // post-relu activations (fp32)
__device__ int   g_cnt[N_NODES];                  // per-node in-degree
__device__ int   g_slot[(size_t)N_NODES * SLOTS]; // per-node src lists (padded)
__device__ float g_sum[FEAT];
__device__ float g_sumsq[FEAT];

// ---------------- helpers ---------------------------------------------------
__device__ __forceinline__ ull pk(float x) {
    ull r; asm("mov.b64 %0, {%1, %1};" : "=l"(r) : "f"(x)); return r;
}
__device__ __forceinline__ void ffma2(ull& d, ull a, ull b) {
    asm("fma.rn.f32x2 %0, %1, %2, %3;" : "=l"(d) : "l"(a), "l"(b), "l"(d));
}
__device__ __forceinline__ float2 up(ull v) {
    float2 p; asm("mov.b64 {%0, %1}, %2;" : "=f"(p.x), "=f"(p.y) : "l"(v)); return p;
}

// ---------------- K0: zero phis, BN accumulators, in-degree counters --------
#define NZERO (N_GRAPHS * FEAT + 2 * FEAT + N_NODES)
__global__ void k_zero(float* __restrict__ phis) {
    int i = blockIdx.x * blockDim.x + threadIdx.x;
    if (i < N_GRAPHS * FEAT)                  phis[i] = 0.f;
    else if (i < N_GRAPHS * FEAT + FEAT)      g_sum[i - N_GRAPHS * FEAT] = 0.f;
    else if (i < N_GRAPHS * FEAT + 2 * FEAT)  g_sumsq[i - N_GRAPHS * FEAT - FEAT] = 0.f;
    else if (i < NZERO)                       g_cnt[i - N_GRAPHS * FEAT - 2 * FEAT] = 0;
}

// ---------------- K1: build per-node src lists ------------------------------
__global__ void k_build(const int* __restrict__ src, const int* __restrict__ dst) {
    int e = blockIdx.x * blockDim.x + threadIdx.x;
    if (e >= N_EDGES) return;
    int d = __ldg(&dst[e]);
    int s = __ldg(&src[e]);
    int pos = atomicAdd(&g_cnt[d], 1);
    g_slot[(size_t)d * SLOTS + pos] = s;
}

// ---------------- K2: Z = (h*norm) @ W  (fp16 output, f32x2 FMA) ------------
// 256 threads = 8 warps. Tile 128x128, K=128 full.
// Warp w: cols 16w..16w+15 (broadcast W). Lane l: rows 4l..4l+3.
__global__ void __launch_bounds__(256, 1)
k_gemm(const float* __restrict__ h, const float* __restrict__ norm,
       const float* __restrict__ Wg) {
    extern __shared__ float sm[];
    float* As = sm;             // [k][m], stride 128
    float* Ws = sm + 16384;     // [k][c], stride 128
    int tid = threadIdx.x;
    int rowbase = blockIdx.x * 128;

    {
        int r = tid & 127, half = tid >> 7;
        int gr = rowbase + r;
        bool ok = (gr < N_NODES);
        float nm = ok ? __ldg(&norm[gr]) : 0.f;
        const float4* arow = (const float4*)(h + (size_t)gr * FEAT);
        #pragma unroll
        for (int j = 0; j < 16; j++) {
            int k = half * 64 + j * 4;
            float4 v = ok ? __ldg(&arow[k >> 2]) : make_float4(0.f, 0.f, 0.f, 0.f);
            As[(k + 0) * 128 + r] = v.x * nm;
            As[(k + 1) * 128 + r] = v.y * nm;
            As[(k + 2) * 128 + r] = v.z * nm;
            As[(k + 3) * 128 + r] = v.w * nm;
        }
    }
    #pragma unroll
    for (int it = 0; it < 16; it++) {
        int g = tid + 256 * it;            // float4 index, 4096 total
        int k = g >> 5, c = (g & 31) * 4;
        *(float4*)&Ws[k * 128 + c] = __ldg(&((const float4*)Wg)[g]);
    }
    __syncthreads();

    int w = tid >> 5, lane = tid & 31;
    int c0 = w * 16, r0 = lane * 4;

    ull acc[32];
    #pragma unroll
    for (int i = 0; i < 32; i++) acc[i] = 0ull;

    #pragma unroll 4
    for (int k = 0; k < 128; k++) {
        float4 av = *(const float4*)&As[k * 128 + r0];
        ull ad[4] = {pk(av.x), pk(av.y), pk(av.z), pk(av.w)};
        const ull* wp = (const ull*)&Ws[k * 128 + c0];
        ull wd[8];
        #pragma unroll
        for (int c2 = 0; c2 < 8; c2++) wd[c2] = wp[c2];
        #pragma unroll
        for (int r = 0; r < 4; r++)
            #pragma unroll
            for (int c2 = 0; c2 < 8; c2++)
                ffma2(acc[r * 8 + c2], ad[r], wd[c2]);
    }

    // store Z rows as half2
    #pragma unroll
    for (int r = 0; r < 4; r++) {
        int row = rowbase + r0 + r;
        if (row < N_NODES) {
            uint st[8];
            #pragma unroll
            for (int c2 = 0; c2 < 8; c2++) {
                float2 p = up(acc[r * 8 + c2]);
                __half2 hv = __floats2half2_rn(p.x, p.y);   // low = even col
                st[c2] = *(uint*)&hv;
            }
            uint* zr = g_Z + (size_t)row * 64 + c0 / 2;
            ((uint4*)zr)[0] = make_uint4(st[0], st[1], st[2], st[3]);
            ((uint4*)zr)[1] = make_uint4(st[4], st[5], st[6], st[7]);
        }
    }
}

// ---------------- K3: Y[v] = relu(norm[v]*sum_nbr Z[s] + b), BN stats -------
// One warp handles a PAIR of nodes; occupancy forced to 6 CTAs/SM.
#define GBLK 2048
__device__ __forceinline__ void acc_z(float4& a, int s, int lane) {
    uint2 q = __ldg(&((const uint2*)(g_Z + (size_t)s * 64))[lane]);
    float2 f0 = __half22float2(*(__half2*)&q.x);
    float2 f1 = __half22float2(*(__half2*)&q.y);
    a.x += f0.x; a.y += f0.y; a.z += f1.x; a.w += f1.y;
}
__global__ void __launch_bounds__(256, 6)
k_gather(const float* __restrict__ norm, const float* __restrict__ bg) {
    __shared__ float S1[8 * 128];
    __shared__ float S2[8 * 128];
    int lane = threadIdx.x & 31;
    int wid  = threadIdx.x >> 5;
    int gw   = blockIdx.x * 8 + wid;
    const int nw = GBLK * 8;

    float4 bv = __ldg(&((const float4*)bg)[lane]);
    float4 cs = make_float4(0.f, 0.f, 0.f, 0.f);
    float4 cq = make_float4(0.f, 0.f, 0.f, 0.f);

    for (int v0 = gw * 2; v0 < N_NODES; v0 += nw * 2) {
        int v1 = v0 + 1;                       // N_NODES even -> always valid
        int c0 = __ldg(&g_cnt[v0]), c1 = __ldg(&g_cnt[v1]);
        const int* sl0 = g_slot + (size_t)v0 * SLOTS;
        const int* sl1 = g_slot + (size_t)v1 * SLOTS;
        int ms0 = (lane < c0) ? __ldg(&sl0[lane]) : 0;
        int ms1 = (lane < c1) ? __ldg(&sl1[lane]) : 0;

        float4 a0 = make_float4(0.f, 0.f, 0.f, 0.f);
        float4 a1 = make_float4(0.f, 0.f, 0.f, 0.f);
        int cc0 = min(c0, 32), cc1 = min(c1, 32);
        int m = max(cc0, cc1);
        #pragma unroll 4
        for (int i = 0; i < m; i++) {
            if (i < cc0) { int s = __shfl_sync(0xffffffffu, ms0, i); acc_z(a0, s, lane); }
            if (i < cc1) { int s = __shfl_sync(0xffffffffu, ms1, i); acc_z(a1, s, lane); }
        }
        for (int i = 32; i < c0; i++) { int s = __ldg(&sl0[i]); acc_z(a0, s, lane); }
        for (int i = 32; i < c1; i++) { int s = __ldg(&sl1[i]); acc_z(a1, s, lane); }

        float n0 = __ldg(&norm[v0]);
        float n1 = __ldg(&norm[v1]);
        float4 y0, y1;
        y0.x = fmaxf(a0.x * n0 + bv.x, 0.f); y0.y = fmaxf(a0.y * n0 + bv.y, 0.f);
        y0.z = fmaxf(a0.z * n0 + bv.z, 0.f); y0.w = fmaxf(a0.w * n0 + bv.w, 0.f);
        y1.x = fmaxf(a1.x * n1 + bv.x, 0.f); y1.y = fmaxf(a1.y * n1 + bv.y, 0.f);
        y1.z = fmaxf(a1.z * n1 + bv.z, 0.f); y1.w = fmaxf(a1.w * n1 + bv.w, 0.f);
        ((float4*)(g_Y + (size_t)v0 * FEAT))[lane] = y0;
        ((float4*)(g_Y + (size_t)v1 * FEAT))[lane] = y1;
        cs.x += y0.x + y1.x; cs.y += y0.y + y1.y;
        cs.z += y0.z + y1.z; cs.w += y0.w + y1.w;
        cq.x += y0.x * y0.x + y1.x * y1.x; cq.y += y0.y * y0.y + y1.y * y1.y;
        cq.z += y0.z * y0.z + y1.z * y1.z; cq.w += y0.w * y0.w + y1.w * y1.w;
    }

    *(float4*)&S1[wid * 128 + lane * 4] = cs;
    *(float4*)&S2[wid * 128 + lane * 4] = cq;
    __syncthreads();
    int tid = threadIdx.x;
    if (tid < 128) {
        float s = 0.f, q = 0.f;
        #pragma unroll
        for (int y = 0; y < 8; y++) { s += S1[y * 128 + tid]; q += S2[y * 128 + tid]; }
        atomicAdd(&g_sum[tid], s);
        atomicAdd(&g_sumsq[tid], q);
    }
}

// ---------------- K4: BN-finalize (per-warp) + apply + pooled segment sum ---
#define OCHUNK 64
__global__ void __launch_bounds__(256)
k_out(const int* __restrict__ gid, const float* __restrict__ gamma,
      const float* __restrict__ beta, float* __restrict__ xout,
      float* __restrict__ phis) {
    int lane = threadIdx.x & 31;
    int wid  = threadIdx.x >> 5;
    int chunk = blockIdx.x * 8 + wid;
    int r0 = chunk * OCHUNK;
    if (r0 >= N_NODES) return;
    int rend = min(r0 + OCHUNK, N_NODES);

    // recompute scale/shift locally (tiny, L2-cached)
    float4 s1 = *(const float4*)&g_sum[lane * 4];
    float4 s2 = *(const float4*)&g_sumsq[lane * 4];
    float4 gm = __ldg(&((const float4*)gamma)[lane]);
    float4 bt = __ldg(&((const float4*)beta)[lane]);
    const float inv = 1.f / N_NODES;
    float4 sc, sh;
    {
        float m, v;
        m = s1.x * inv; v = s2.x * inv - m * m; sc.x = gm.x * rsqrtf(v + BN_EPS); sh.x = bt.x - m * sc.x;
        m = s1.y * inv; v = s2.y * inv - m * m; sc.y = gm.y * rsqrtf(v + BN_EPS); sh.y = bt.y - m * sc.y;
        m = s1.z * inv; v = s2.z * inv - m * m; sc.z = gm.z * rsqrtf(v + BN_EPS); sh.z = bt.z - m * sc.z;
        m = s1.w * inv; v = s2.w * inv - m * m; sc.w = gm.w * rsqrtf(v + BN_EPS); sh.w = bt.w - m * sc.w;
    }

    float4 acc = make_float4(0.f, 0.f, 0.f, 0.f);
    int gcur = __ldg(&gid[r0]);

    #pragma unroll 4
    for (int r = r0; r < rend; r++) {
        int g = __ldg(&gid[r]);
        float4 y = ((const float4*)(g_Y + (size_t)r * FEAT))[lane];
        float4 v;
        v.x = y.x * sc.x + sh.x; v.y = y.y * sc.y + sh.y;
        v.z = y.z * sc.z + sh.z; v.w = y.w * sc.w + sh.w;
        ((float4*)(xout + (size_t)r * FEAT))[lane] = v;
        if (g != gcur) {
            float* pp = phis + (size_t)gcur * FEAT + lane * 4;
            atomicAdd(pp + 0, acc.x); atomicAdd(pp + 1, acc.y);
            atomicAdd(pp + 2, acc.z); atomicAdd(pp + 3, acc.w);
            acc = make_float4(0.f, 0.f, 0.f, 0.f);
            gcur = g;
        }
        acc.x += v.x; acc.y += v.y; acc.z += v.z; acc.w += v.w;
    }
    float* pp = phis + (size_t)gcur * FEAT + lane * 4;
    atomicAdd(pp + 0, acc.x); atomicAdd(pp + 1, acc.y);
    atomicAdd(pp + 2, acc.z); atomicAdd(pp + 3, acc.w);
}

// ---------------- launch -----------------------------------------------------
extern "C" void kernel_launch(void* const* d_in, const int* in_sizes, int n_in,
                              void* d_out, int out_size) {
    const float* h     = (const float*)d_in[0];
    const float* norm  = (const float*)d_in[1];
    const float* W     = (const float*)d_in[2];
    const float* b     = (const float*)d_in[3];
    const float* gamma = (const float*)d_in[4];
    const float* beta  = (const float*)d_in[5];
    const int*   src   = (const int*)d_in[6];
    const int*   dst   = (const int*)d_in[7];
    const int*   gid   = (const int*)d_in[8];
    float* xout = (float*)d_out;
    float* phis = xout + (size_t)N_NODES * FEAT;

    const int smem_gemm = 2 * 128 * 128 * sizeof(float);   // 131072 B
    cudaFuncSetAttribute(k_gemm, cudaFuncAttributeMaxDynamicSharedMemorySize, smem_gemm);

    k_zero<<<(NZERO + 255) / 256, 256>>>(phis);
    k_build<<<(N_EDGES + 255) / 256, 256>>>(src, dst);
    k_gemm<<<(N_NODES + 127) / 128, 256, smem_gemm>>>(h, norm, W);
    k_gather<<<GBLK, 256>>>(norm, b);
    k_out<<<(N_NODES + OCHUNK * 8 - 1) / (OCHUNK * 8), 256>>>(gid, gamma, beta, xout, phis);
}